// round 7
// baseline (speedup 1.0000x reference)
#include <cuda_runtime.h>
#include <cuda_bf16.h>
#include <math.h>
#include <stdint.h>

// ---------------- problem constants ----------------
#define T_    4
#define B_    32
#define N_    196
#define C_    384
#define H_    8
#define D_    48
#define HID_  1536
#define TB_   128           // T*B
#define NC_   75264         // N*C
#define BNC_  2408448       // B*N*C
#define TBN_  25088         // T*B*N
#define BN_   6272          // B*N
#define MH_   9633792       // BN_*HID_ == TBN_*C_

// ---------------- scratch (device globals) ----------------
__device__ float g_bq[MH_];
__device__ float g_bk[MH_];
__device__ float g_bv[MH_];
__device__ float g_ab[MH_];
__device__ float g_af[MH_];
__device__ float g_curr[4 * MH_];
__device__ float g_syn[MH_];
__device__ float g_mem[MH_];
__device__ float g_R[MH_];
__device__ float g_l[MH_];
__device__ float g_ga[MH_];
__device__ float g_gl[MH_];
__device__ float g_fu[MH_];
__device__ float g_o[MH_];
__device__ float g_part[98 * 768];
__device__ float g_stats[768];
// int8 spike buffers (exactly 0/1)
__device__ int8_t g_sq[MH_];
__device__ int8_t g_sk[MH_];
__device__ int8_t g_sv[MH_];
__device__ int8_t g_abb[MH_];
__device__ int8_t g_afb[MH_];
__device__ int8_t g_spkb[4 * MH_];
__device__ int8_t g_lfb[MH_];
// 4-digit int8 weight decompositions (binary-input GEMMs only)
#define CC_ (C_ * C_)
#define HC_ (HID_ * C_)
#define HH_ (HID_ * HID_)
__device__ int8_t g_apd[4 * CC_];
__device__ int8_t g_watd[4 * CC_];
__device__ int8_t g_wlsd[4 * CC_];
__device__ int8_t g_fc2d[4 * HC_];
__device__ int8_t g_recd[4 * HH_];

// ---------------- helpers ----------------
__device__ __forceinline__ uint32_t smem_to_u32(const void* p) {
    uint32_t a;
    asm("{ .reg .u64 t; cvta.to.shared.u64 t, %1; cvt.u32.u64 %0, t; }" : "=r"(a) : "l"(p));
    return a;
}

#define LDSM4(R0, R1, R2, R3, ADDR) \
    asm volatile("ldmatrix.sync.aligned.m8n8.x4.shared.b16 {%0,%1,%2,%3}, [%4];" \
                 : "=r"(R0), "=r"(R1), "=r"(R2), "=r"(R3) : "r"(ADDR))

#define IMMA16832(D, A0, A1, A2, A3, B0, B1) \
    asm volatile("mma.sync.aligned.m16n8k32.row.col.s32.s8.s8.s32 " \
                 "{%0,%1,%2,%3}, {%4,%5,%6,%7}, {%8,%9}, {%0,%1,%2,%3};" \
                 : "+r"((D)[0]), "+r"((D)[1]), "+r"((D)[2]), "+r"((D)[3]) \
                 : "r"(A0), "r"(A1), "r"(A2), "r"(A3), "r"(B0), "r"(B1))

// ====== IMMA exact 4-digit GEMM: C[M,Nn] = A(0/1) @ W[Nn,K]^T + bias ======
// W decomposed as w = 2 * sum_j d_j * 128^-(j+1), digits int8 (exact).
// int32 accumulation (exact); fp32 fold once per digit (at ch+1 % nch == 0).
// 128x128 tile, 8 warps (2m x 4n), K-chunks of 32, double-buffered smem.
__global__ __launch_bounds__(256, 1)
void igemm4_nt(const int8_t* __restrict__ A, const int8_t* __restrict__ Wd,
               const float* __restrict__ bias, float* __restrict__ C,
               int M, int Nn, int K) {
    __shared__ __align__(16) char sm[24576];
    const int tid = threadIdx.x;
    const int lane = tid & 31;
    const int wid = tid >> 5;
    const int warp_m = wid & 1;
    const int warp_n = wid >> 1;
    const int bm = blockIdx.y * 128;
    const int bn = blockIdx.x * 128;
    const uint32_t smb = smem_to_u32(sm);

    float accf[4][4][4];
    int   acci[4][4][4];
#pragma unroll
    for (int i = 0; i < 4; i++)
#pragma unroll
        for (int j = 0; j < 4; j++)
#pragma unroll
            for (int r = 0; r < 4; r++) { accf[i][j][r] = 0.0f; acci[i][j][r] = 0; }

    const int nch = K >> 5;          // 32-wide K chunks per digit
    const int totch = 4 * nch;
    const size_t wstride = (size_t)Nn * K;

    const int grow = tid >> 1;       // 0..127
    const int gh = tid & 1;          // 16B half of 32B chunk
    const int arow0 = warp_m * 64 + (lane & 15);
    const int akc0 = lane >> 4;
    const int brow0 = warp_n * 32 + ((lane & 7) | ((lane & 16) >> 1));
    const int bkc0 = (lane >> 3) & 1;
    const int sdst = grow * 48 + gh * 16;

    const float wj_tab[4] = {0.015625f, 1.220703125e-4f,
                             9.5367431640625e-7f, 7.450580596923828e-9f};

    // prologue: chunk 0 (digit 0, kc 0) -> buffer 0
    {
        uint4 va = *(const uint4*)(A + (size_t)(bm + grow) * K + gh * 16);
        uint4 vw = *(const uint4*)(Wd + (size_t)(bn + grow) * K + gh * 16);
        *(uint4*)(sm + sdst) = va;
        *(uint4*)(sm + 12288 + sdst) = vw;
    }
    __syncthreads();

    int kc_next = 1, dig_next = 0;
    if (kc_next == nch) { kc_next = 0; dig_next = 1; }

    for (int ch = 0; ch < totch; ch++) {
        const int cur = ch & 1;
        const bool more = (ch + 1 < totch);
        uint4 pa, pw;
        if (more) {
            pa = *(const uint4*)(A + (size_t)(bm + grow) * K + kc_next * 32 + gh * 16);
            pw = *(const uint4*)(Wd + (size_t)dig_next * wstride
                                 + (size_t)(bn + grow) * K + kc_next * 32 + gh * 16);
        }
        // compute on buffer cur (one k32 step)
        const uint32_t baseA = smb + (uint32_t)cur * 6144u;
        const uint32_t baseB = smb + 12288u + (uint32_t)cur * 6144u;
        uint32_t a[4][4];
#pragma unroll
        for (int mt = 0; mt < 4; mt++) {
            const uint32_t ad = baseA + (uint32_t)(arow0 + mt * 16) * 48u + (uint32_t)akc0 * 16u;
            LDSM4(a[mt][0], a[mt][1], a[mt][2], a[mt][3], ad);
        }
        uint32_t b[2][4];
#pragma unroll
        for (int np = 0; np < 2; np++) {
            const uint32_t bd = baseB + (uint32_t)(brow0 + np * 16) * 48u + (uint32_t)bkc0 * 16u;
            LDSM4(b[np][0], b[np][1], b[np][2], b[np][3], bd);
        }
#pragma unroll
        for (int mt = 0; mt < 4; mt++) {
#pragma unroll
            for (int nt = 0; nt < 4; nt++) {
                const int np = nt >> 1;
                const int hb = (nt & 1) * 2;
                IMMA16832(acci[mt][nt], a[mt][0], a[mt][1], a[mt][2], a[mt][3],
                          b[np][hb], b[np][hb + 1]);
            }
        }
        // digit boundary: fold int32 -> fp32 (FIX: modulo, nch is not a power of 2)
        if (((ch + 1) % nch) == 0) {
            const float wj = wj_tab[ch / nch];
#pragma unroll
            for (int mt = 0; mt < 4; mt++)
#pragma unroll
                for (int nt = 0; nt < 4; nt++)
#pragma unroll
                    for (int r = 0; r < 4; r++) {
                        accf[mt][nt][r] = fmaf((float)acci[mt][nt][r], wj, accf[mt][nt][r]);
                        acci[mt][nt][r] = 0;
                    }
        }
        if (more) {
            const int nxt = cur ^ 1;
            *(uint4*)(sm + nxt * 6144 + sdst) = pa;
            *(uint4*)(sm + 12288 + nxt * 6144 + sdst) = pw;
            __syncthreads();
            if (++kc_next == nch) { kc_next = 0; dig_next++; }
        }
    }

    // epilogue with bias
#pragma unroll
    for (int mt = 0; mt < 4; mt++) {
        const int m0 = bm + warp_m * 64 + mt * 16 + (lane >> 2);
#pragma unroll
        for (int nt = 0; nt < 4; nt++) {
            const int n0 = bn + warp_n * 32 + nt * 8 + 2 * (lane & 3);
            const float2 bv = *(const float2*)&bias[n0];
            float2 v0, v1;
            v0.x = accf[mt][nt][0] + bv.x; v0.y = accf[mt][nt][1] + bv.y;
            v1.x = accf[mt][nt][2] + bv.x; v1.y = accf[mt][nt][3] + bv.y;
            *(float2*)&C[(size_t)m0 * Nn + n0] = v0;
            *(float2*)&C[(size_t)(m0 + 8) * Nn + n0] = v1;
        }
    }
}

// ================= fp32 SGEMM (round-2 proven, bitwise unchanged) =================
#define BM 128
#define BN 128
#define BK 8

__global__ __launch_bounds__(256, 2)
void sgemm_nt(const float* __restrict__ A, const float* __restrict__ W,
              const float* __restrict__ bias, float* __restrict__ C,
              int M, int N, int K) {
    __shared__ float As[2][BK][BM];
    __shared__ float Bs[2][BK][BN];

    const int tid = threadIdx.x;
    const int bm = blockIdx.y * BM;
    const int bn = blockIdx.x * BN;

    const int lr = tid >> 1;
    const int lc = (tid & 1) * 4;
    const float* Ap = A + (size_t)(bm + lr) * K + lc;
    const float* Wp = W + (size_t)(bn + lr) * K + lc;

    const int tx = tid & 15;
    const int ty = tid >> 4;

    float acc[8][8] = {};

    float4 av = *(const float4*)Ap;
    float4 wv = *(const float4*)Wp;
    As[0][lc + 0][lr] = av.x; As[0][lc + 1][lr] = av.y;
    As[0][lc + 2][lr] = av.z; As[0][lc + 3][lr] = av.w;
    Bs[0][lc + 0][lr] = wv.x; Bs[0][lc + 1][lr] = wv.y;
    Bs[0][lc + 2][lr] = wv.z; Bs[0][lc + 3][lr] = wv.w;
    __syncthreads();

    const int nk = K / BK;
    for (int kt = 0; kt < nk; kt++) {
        const int cur = kt & 1;
        if (kt + 1 < nk) {
            av = *(const float4*)(Ap + (size_t)(kt + 1) * BK);
            wv = *(const float4*)(Wp + (size_t)(kt + 1) * BK);
        }
#pragma unroll
        for (int kk = 0; kk < BK; kk++) {
            float4 a0 = *(const float4*)&As[cur][kk][ty * 4];
            float4 a1 = *(const float4*)&As[cur][kk][ty * 4 + 64];
            float4 b0 = *(const float4*)&Bs[cur][kk][tx * 4];
            float4 b1 = *(const float4*)&Bs[cur][kk][tx * 4 + 64];
            float a[8] = {a0.x, a0.y, a0.z, a0.w, a1.x, a1.y, a1.z, a1.w};
            float b[8] = {b0.x, b0.y, b0.z, b0.w, b1.x, b1.y, b1.z, b1.w};
#pragma unroll
            for (int i = 0; i < 8; i++)
#pragma unroll
                for (int j = 0; j < 8; j++)
                    acc[i][j] += a[i] * b[j];
        }
        if (kt + 1 < nk) {
            const int nxt = cur ^ 1;
            As[nxt][lc + 0][lr] = av.x; As[nxt][lc + 1][lr] = av.y;
            As[nxt][lc + 2][lr] = av.z; As[nxt][lc + 3][lr] = av.w;
            Bs[nxt][lc + 0][lr] = wv.x; Bs[nxt][lc + 1][lr] = wv.y;
            Bs[nxt][lc + 2][lr] = wv.z; Bs[nxt][lc + 3][lr] = wv.w;
            __syncthreads();
        }
    }

#pragma unroll
    for (int i = 0; i < 8; i++) {
        const int row = bm + ty * 4 + (i & 3) + ((i >> 2) << 6);
#pragma unroll
        for (int jb = 0; jb < 2; jb++) {
            const int col = bn + tx * 4 + jb * 64;
            float4 bv4 = *(const float4*)&bias[col];
            float4 v;
            v.x = acc[i][jb * 4 + 0] + bv4.x;
            v.y = acc[i][jb * 4 + 1] + bv4.y;
            v.z = acc[i][jb * 4 + 2] + bv4.z;
            v.w = acc[i][jb * 4 + 3] + bv4.w;
            *(float4*)&C[(size_t)row * N + col] = v;
        }
    }
}

// ---------------- exact 4-digit int8 decomposition: w = 2 * sum d_j 128^-(j+1) ----------------
__global__ void split_digits(const float* __restrict__ w, int8_t* __restrict__ d, long n) {
    long i = (long)blockIdx.x * blockDim.x + threadIdx.x;
    if (i >= n) return;
    float r = w[i] * 0.5f;            // exact (|w| < 2)
#pragma unroll
    for (int j = 0; j < 4; j++) {
        float rj = r * 128.0f;        // exact
        float dj = rintf(rj);
        r = rj - dj;                  // exact
        d[(size_t)j * n + i] = (int8_t)(int)dj;
    }
}

// ---------------- LIF scan: float in -> int8 spikes out ----------------
__global__ void lif_seq_i8(const float* __restrict__ in, int8_t* __restrict__ out,
                           int steps, long stride, long nelem,
                           const float* __restrict__ lif_w, int widx) {
    long idx = (long)blockIdx.x * blockDim.x + threadIdx.x;
    if (idx >= nelem) return;
    const float decay = 1.0f / (1.0f + expf(-lif_w[widx]));
    float v = 0.0f;
    float xs[4];
#pragma unroll
    for (int t = 0; t < 4; t++)
        if (t < steps) xs[t] = in[(long)t * stride + idx];
    for (int t = 0; t < steps; t++) {
        float x = xs[t & 3];
        if (t + 4 < steps) xs[t & 3] = in[(long)(t + 4) * stride + idx];
        v = v + (x - v) * decay;
        int8_t s = (v >= 1.0f) ? 1 : 0;
        out[(long)t * stride + idx] = s;
        if (s) v = 0.0f;
    }
}

// ---------------- spiking attention (int8 spikes), one block per (tb, h) ----------------
__global__ __launch_bounds__(256)
void attn_kernel(const int8_t* __restrict__ sq, const int8_t* __restrict__ sk,
                 const int8_t* __restrict__ sv, float* __restrict__ abuf) {
    const int tb = blockIdx.x >> 3;
    const int h = blockIdx.x & 7;
    __shared__ unsigned long long qb[N_], kb[N_], vb[N_];
    __shared__ unsigned char cnt[N_ * 200];
    const int tid = threadIdx.x;

    for (int i = tid; i < N_; i += 256) { qb[i] = 0ull; kb[i] = 0ull; vb[i] = 0ull; }
    __syncthreads();

    const long base = (long)tb * NC_ + h * D_;
    for (int e = tid; e < N_ * D_; e += 256) {
        int n = e / D_, d = e % D_;
        long off = base + (long)n * C_ + d;
        unsigned long long bit = 1ull << d;
        if (sq[off]) atomicOr(&qb[n], bit);
        if (sk[off]) atomicOr(&kb[n], bit);
        if (sv[off]) atomicOr(&vb[n], bit);
    }
    __syncthreads();

    for (int i = tid; i < N_ * N_; i += 256) {
        int n = i / N_, m = i - n * N_;
        cnt[n * 200 + m] = (unsigned char)__popcll(qb[n] & kb[m]);
    }
    __syncthreads();

    const float scale = 0.14433756729740643f;  // 48^-0.5
    for (int o = tid; o < N_ * D_; o += 256) {
        int n = o / D_, d = o - n * D_;
        const unsigned char* crow = &cnt[n * 200];
        int acc = 0;
#pragma unroll 4
        for (int m = 0; m < N_; m++)
            acc += (int)crow[m] * (int)((vb[m] >> d) & 1ull);
        abuf[(long)tb * NC_ + h * (D_ * N_) + d * N_ + n] = scale * (float)acc;
    }
}

// ---------------- LSM elementwise steps (int8 spikes) ----------------
__global__ void lsm_step0(const float* __restrict__ curr, const float* __restrict__ rec_b,
                          float* __restrict__ syn, float* __restrict__ mem,
                          int8_t* __restrict__ spk) {
    long idx = (long)blockIdx.x * blockDim.x + threadIdx.x;
    if (idx >= (long)MH_) return;
    int hc = (int)(idx % HID_);
    float s = curr[idx] + rec_b[hc];
    syn[idx] = s;
    mem[idx] = s;
    spk[idx] = (s - 1.0f >= 0.0f) ? 1 : 0;
}

__global__ void lsm_step(const float* __restrict__ curr_t, const float* __restrict__ R,
                         float* __restrict__ syn, float* __restrict__ mem,
                         const int8_t* __restrict__ spk_prev, int8_t* __restrict__ spk_out) {
    long idx = (long)blockIdx.x * blockDim.x + threadIdx.x;
    if (idx >= (long)MH_) return;
    float sp = spk_prev[idx] ? 1.0f : 0.0f;
    float s = 0.9f * syn[idx] + curr_t[idx] + R[idx];
    float m = 0.8f * mem[idx] + s - sp;
    syn[idx] = s;
    mem[idx] = m;
    spk_out[idx] = (m - 1.0f >= 0.0f) ? 1 : 0;
}

// ---------------- BatchNorm stats (deterministic 2-stage) ----------------
__global__ void bn_partial(const float* __restrict__ X, float* __restrict__ part) {
    int c = threadIdx.x;
    long r0 = (long)blockIdx.x * 256;
    float s = 0.0f, s2 = 0.0f;
    for (int r = 0; r < 256; r++) {
        float v = X[(r0 + r) * C_ + c];
        s += v;
        s2 += v * v;
    }
    part[blockIdx.x * 768 + c] = s;
    part[blockIdx.x * 768 + 384 + c] = s2;
}

__global__ void bn_finalize(const float* __restrict__ part, float* __restrict__ stats) {
    int c = threadIdx.x;
    float s = 0.0f, s2 = 0.0f;
    for (int p = 0; p < 98; p++) {
        s += part[p * 768 + c];
        s2 += part[p * 768 + 384 + c];
    }
    const float inv = 1.0f / 25088.0f;
    float m = s * inv;
    float var = s2 * inv - m * m;
    stats[c] = m;
    stats[384 + c] = 1.0f / sqrtf(var + 1e-5f);
}

// ---------------- BN-apply + 4-step LIF -> int8 spikes ----------------
__global__ void bn_lif4_i8(const float* __restrict__ lin, int8_t* __restrict__ out,
                           const float* __restrict__ stats,
                           const float* __restrict__ gamma, const float* __restrict__ beta,
                           const float* __restrict__ lif_w, int widx) {
    long idx = (long)blockIdx.x * blockDim.x + threadIdx.x;
    if (idx >= (long)BNC_) return;
    int c = (int)(idx % C_);
    float mu = stats[c], rstd = stats[384 + c];
    float gg = gamma[c], bb = beta[c];
    float decay = 1.0f / (1.0f + expf(-lif_w[widx]));
    float v = 0.0f;
    float xs[4];
#pragma unroll
    for (int t = 0; t < 4; t++) xs[t] = lin[(long)t * BNC_ + idx];
#pragma unroll
    for (int t = 0; t < 4; t++) {
        float xv = (xs[t] - mu) * rstd * gg + bb;
        v = v + (xv - v) * decay;
        int8_t s = (v >= 1.0f) ? 1 : 0;
        if (s) v = 0.0f;
        out[(long)t * BNC_ + idx] = s;
    }
}

// ---------------- BN-apply + 4-step LIF + residual -> float out ----------------
__global__ void bn_lif4_res(const float* __restrict__ lin, float* __restrict__ out,
                            const float* __restrict__ stats,
                            const float* __restrict__ gamma, const float* __restrict__ beta,
                            const float* __restrict__ lif_w, int widx,
                            const float* __restrict__ xadd) {
    long idx = (long)blockIdx.x * blockDim.x + threadIdx.x;
    if (idx >= (long)BNC_) return;
    int c = (int)(idx % C_);
    float mu = stats[c], rstd = stats[384 + c];
    float gg = gamma[c], bb = beta[c];
    float decay = 1.0f / (1.0f + expf(-lif_w[widx]));
    float v = 0.0f;
    float xs[4];
#pragma unroll
    for (int t = 0; t < 4; t++) xs[t] = lin[(long)t * BNC_ + idx];
#pragma unroll
    for (int t = 0; t < 4; t++) {
        long o = (long)t * BNC_ + idx;
        float xv = (xs[t] - mu) * rstd * gg + bb;
        v = v + (xv - v) * decay;
        float s = (v >= 1.0f) ? 1.0f : 0.0f;
        v *= (1.0f - s);
        out[o] = xadd[o] + s;
    }
}

// ---------------- ARIG fusion: int8 spikes + float gates -> float fu ----------------
__global__ void fuse_kernel(const int8_t* __restrict__ afb, const int8_t* __restrict__ lfb,
                            const float* __restrict__ ga, const float* __restrict__ gl,
                            float* __restrict__ fu) {
    long idx = (long)blockIdx.x * blockDim.x + threadIdx.x;
    if (idx >= (long)MH_) return;
    float a = afb[idx] ? 1.0f : 0.0f;
    float l = lfb[idx] ? 1.0f : 0.0f;
    float gate_attn = 1.0f / (1.0f + expf(-gl[idx]));
    float gate_lsm  = 1.0f / (1.0f + expf(-ga[idx]));
    fu[idx] = a * gate_attn + l * gate_lsm;
}

// ---------------- launch ----------------
extern "C" void kernel_launch(void* const* d_in, const int* in_sizes, int n_in,
                              void* d_out, int out_size) {
    const float* x      = (const float*)d_in[0];
    const float* q_w    = (const float*)d_in[1];
    const float* q_b    = (const float*)d_in[2];
    const float* k_w    = (const float*)d_in[3];
    const float* k_b    = (const float*)d_in[4];
    const float* v_w    = (const float*)d_in[5];
    const float* v_b    = (const float*)d_in[6];
    const float* ap_w   = (const float*)d_in[7];
    const float* ap_b   = (const float*)d_in[8];
    const float* fc1_w  = (const float*)d_in[9];
    const float* fc1_b  = (const float*)d_in[10];
    const float* rec_w  = (const float*)d_in[11];
    const float* rec_b  = (const float*)d_in[12];
    const float* fc2_w  = (const float*)d_in[13];
    const float* fc2_b  = (const float*)d_in[14];
    const float* bnl_g  = (const float*)d_in[15];
    const float* bnl_b  = (const float*)d_in[16];
    const float* watt_w = (const float*)d_in[17];
    const float* watt_b = (const float*)d_in[18];
    const float* wlsm_w = (const float*)d_in[19];
    const float* wlsm_b = (const float*)d_in[20];
    const float* fp_w   = (const float*)d_in[21];
    const float* fp_b   = (const float*)d_in[22];
    const float* bnf_g  = (const float*)d_in[23];
    const float* bnf_b  = (const float*)d_in[24];
    const float* lif_w  = (const float*)d_in[25];
    float* out = (float*)d_out;

    float *bq, *bk, *bv, *ab, *af, *curr, *syn, *mem, *R, *l, *ga, *gl, *fu, *o, *part, *stats;
    cudaGetSymbolAddress((void**)&bq, g_bq);     cudaGetSymbolAddress((void**)&bk, g_bk);
    cudaGetSymbolAddress((void**)&bv, g_bv);     cudaGetSymbolAddress((void**)&ab, g_ab);
    cudaGetSymbolAddress((void**)&af, g_af);     cudaGetSymbolAddress((void**)&curr, g_curr);
    cudaGetSymbolAddress((void**)&syn, g_syn);   cudaGetSymbolAddress((void**)&mem, g_mem);
    cudaGetSymbolAddress((void**)&R, g_R);       cudaGetSymbolAddress((void**)&l, g_l);
    cudaGetSymbolAddress((void**)&ga, g_ga);     cudaGetSymbolAddress((void**)&gl, g_gl);
    cudaGetSymbolAddress((void**)&fu, g_fu);     cudaGetSymbolAddress((void**)&o, g_o);
    cudaGetSymbolAddress((void**)&part, g_part); cudaGetSymbolAddress((void**)&stats, g_stats);
    int8_t *sq, *sk, *sv, *abb, *afb, *spkb, *lfb;
    cudaGetSymbolAddress((void**)&sq, g_sq);     cudaGetSymbolAddress((void**)&sk, g_sk);
    cudaGetSymbolAddress((void**)&sv, g_sv);     cudaGetSymbolAddress((void**)&abb, g_abb);
    cudaGetSymbolAddress((void**)&afb, g_afb);   cudaGetSymbolAddress((void**)&spkb, g_spkb);
    cudaGetSymbolAddress((void**)&lfb, g_lfb);
    int8_t *apd, *watd, *wlsd, *fc2d, *recd;
    cudaGetSymbolAddress((void**)&apd, g_apd);
    cudaGetSymbolAddress((void**)&watd, g_watd);
    cudaGetSymbolAddress((void**)&wlsd, g_wlsd);
    cudaGetSymbolAddress((void**)&fc2d, g_fc2d);
    cudaGetSymbolAddress((void**)&recd, g_recd);

    const int nb75k = (NC_ + 255) / 256;
    const int nbBNC = (BNC_ + 255) / 256;
    const int nbMH  = (MH_ + 255) / 256;
    const dim3 gC(C_ / 128, TBN_ / 128);   // (3, 196)
    const dim3 gH(HID_ / 128, TBN_ / 128); // (12, 196)
    const dim3 gR(HID_ / 128, BN_ / 128);  // (12, 49)

    // ---- exact 4-digit weight decompositions for binary-input GEMMs ----
    split_digits<<<(CC_ + 255) / 256, 256>>>(ap_w,   apd,  CC_);
    split_digits<<<(CC_ + 255) / 256, 256>>>(watt_w, watd, CC_);
    split_digits<<<(CC_ + 255) / 256, 256>>>(wlsm_w, wlsd, CC_);
    split_digits<<<(HC_ + 255) / 256, 256>>>(fc2_w,  fc2d, HC_);
    split_digits<<<(HH_ + 255) / 256, 256>>>(rec_w,  recd, HH_);

    // ---- SSA branch: q/k/v fp32 GEMMs -> 128-step LIF -> attention ----
    sgemm_nt<<<gC, 256>>>(x, q_w, q_b, bq, TBN_, C_, C_);
    sgemm_nt<<<gC, 256>>>(x, k_w, k_b, bk, TBN_, C_, C_);
    sgemm_nt<<<gC, 256>>>(x, v_w, v_b, bv, TBN_, C_, C_);
    lif_seq_i8<<<nb75k, 256>>>(bq, sq, TB_, NC_, NC_, lif_w, 0);
    lif_seq_i8<<<nb75k, 256>>>(bk, sk, TB_, NC_, NC_, lif_w, 1);
    lif_seq_i8<<<nb75k, 256>>>(bv, sv, TB_, NC_, NC_, lif_w, 2);
    attn_kernel<<<TB_ * H_, 256>>>(sq, sk, sv, ab);
    lif_seq_i8<<<nbBNC, 256>>>(ab, abb, T_, BNC_, BNC_, lif_w, 3);
    igemm4_nt<<<gC, 256>>>(abb, apd, ap_b, af, TBN_, C_, C_);
    lif_seq_i8<<<nb75k, 256>>>(af, afb, TB_, NC_, NC_, lif_w, 4);

    // ---- LSM branch ----
    sgemm_nt<<<gH, 256>>>(x, fc1_w, fc1_b, curr, TBN_, HID_, C_);
    lsm_step0<<<nbMH, 256>>>(curr, rec_b, syn, mem, spkb);
    for (int t = 1; t < T_; t++) {
        igemm4_nt<<<gR, 256>>>(spkb + (size_t)(t - 1) * MH_, recd, rec_b, R, BN_, HID_, HID_);
        lsm_step<<<nbMH, 256>>>(curr + (size_t)t * MH_, R, syn, mem,
                                spkb + (size_t)(t - 1) * MH_, spkb + (size_t)t * MH_);
    }
    igemm4_nt<<<gC, 256>>>(spkb, fc2d, fc2_b, l, TBN_, C_, HID_);
    bn_partial<<<98, 384>>>(l, part);
    bn_finalize<<<1, 384>>>(part, stats);
    bn_lif4_i8<<<nbBNC, 256>>>(l, lfb, stats, bnl_g, bnl_b, lif_w, 5);

    // ---- ARIG fusion ----
    igemm4_nt<<<gC, 256>>>(afb, watd, watt_b, ga, TBN_, C_, C_);
    igemm4_nt<<<gC, 256>>>(lfb, wlsd, wlsm_b, gl, TBN_, C_, C_);
    fuse_kernel<<<nbMH, 256>>>(afb, lfb, ga, gl, fu);
    sgemm_nt<<<gC, 256>>>(fu, fp_w, fp_b, o, TBN_, C_, C_);
    bn_partial<<<98, 384>>>(o, part);
    bn_finalize<<<1, 384>>>(part, stats);
    bn_lif4_res<<<nbBNC, 256>>>(o, out, stats, bnf_g, bnf_b, lif_w, 6, x);
}